// round 8
// baseline (speedup 1.0000x reference)
#include <cuda_runtime.h>
#include <cuda_bf16.h>

#define Bb 8
#define Nn 4096
#define Dd 64
#define Gg 32
#define Kk 16

typedef unsigned long long ull;

// scratch
__device__ int g_nbr[Bb * Nn * Kk];
__device__ float g_W1p[64 * 256];   // W1[0:64] - W1[128:192]   (x part)
__device__ float g_W1n[64 * 256];   // W1[64:128] + W1[128:192] (nbr part)

// ---------------------------------------------------------------------------
// f32x2 packed helpers
// ---------------------------------------------------------------------------
__device__ __forceinline__ ull pack2(float a, float b) {
    ull r;
    asm("mov.b64 %0, {%1, %2};" : "=l"(r) : "f"(a), "f"(b));
    return r;
}
__device__ __forceinline__ ull fma2(ull a, ull b, ull c) {
    ull d;
    asm("fma.rn.f32x2 %0, %1, %2, %3;" : "=l"(d) : "l"(a), "l"(b), "l"(c));
    return d;
}
__device__ __forceinline__ float2 unpack2(ull v) {
    float2 f;
    asm("mov.b64 {%0, %1}, %2;" : "=f"(f.x), "=f"(f.y) : "l"(v));
    return f;
}

// ---------------------------------------------------------------------------
// Kernel 1: KNN (blocks 0..255, scalar) + W1 fold (blocks 256..383).
// ---------------------------------------------------------------------------
__global__ __launch_bounds__(128) void knn_prep_kernel(const float* __restrict__ pos,
                                                       const float* __restrict__ W1) {
    const int bx = blockIdx.x;
    if (bx >= 256) {
        const int i = (bx - 256) * 128 + threadIdx.x;   // 0..16383
        const int j = i >> 8;
        const int c = i & 255;
        const float wa = W1[j * 256 + c];
        const float wb = W1[(64 + j) * 256 + c];
        const float wc = W1[(128 + j) * 256 + c];
        g_W1p[i] = wa - wc;
        g_W1n[i] = wb + wc;
        return;
    }

    const int b = bx >> 5;
    const int n = ((bx & 31) << 7) + threadIdx.x;

    const float qx = pos[(b * Nn + n) * 3 + 0];
    const float qy = pos[(b * Nn + n) * 3 + 1];
    const float qz = pos[(b * Nn + n) * 3 + 2];
    const float sqn = __fadd_rn(__fadd_rn(__fmul_rn(qx, qx), __fmul_rn(qy, qy)),
                                __fmul_rn(qz, qz));

    float bd[16];
    int bi[16];
#pragma unroll
    for (int j = 0; j < 16; ++j) { bd[j] = 3.0e38f; bi[j] = 0; }
    float worst = 3.0e38f;
    int wslot = 0;

    __shared__ float4 tile[1024];

    for (int t0 = 0; t0 < Nn; t0 += 1024) {
        __syncthreads();
        for (int i = threadIdx.x; i < 1024; i += 128) {
            const float px = pos[(b * Nn + t0 + i) * 3 + 0];
            const float py = pos[(b * Nn + t0 + i) * 3 + 1];
            const float pz = pos[(b * Nn + t0 + i) * 3 + 2];
            const float sq = __fadd_rn(__fadd_rn(__fmul_rn(px, px), __fmul_rn(py, py)),
                                       __fmul_rn(pz, pz));
            tile[i] = make_float4(px, py, pz, sq);
        }
        __syncthreads();
#pragma unroll 4
        for (int i = 0; i < 1024; ++i) {
            const float4 c = tile[i];
            const int m = t0 + i;
            float dot = __fmaf_rn(qx, c.x, 0.f);
            dot = __fmaf_rn(qy, c.y, dot);
            dot = __fmaf_rn(qz, c.z, dot);
            const float dist = __fsub_rn(__fadd_rn(sqn, c.w), __fmul_rn(2.0f, dot));
            if (dist < worst && m != n) {
#pragma unroll
                for (int j = 0; j < 16; ++j)
                    if (j == wslot) { bd[j] = dist; bi[j] = m; }
                worst = bd[0]; wslot = 0;
#pragma unroll
                for (int j = 1; j < 16; ++j)
                    if (bd[j] > worst) { worst = bd[j]; wslot = j; }
            }
        }
    }

#pragma unroll
    for (int j = 0; j < 16; ++j)
        g_nbr[(b * Nn + n) * 16 + j] = bi[j];
}

// ---------------------------------------------------------------------------
// Kernel 2: fused DenseEdgeConv. 4 points (64 k-lanes), 256 threads, 2 CTAs/SM.
// xn k-invariance exploited: mid 96->32 rows, last 128->64 rows + precomputes.
// ---------------------------------------------------------------------------
#define SROW 68
#define P4 4

#define OFF_NBRT  0                              // [64 c][SROW k]
#define OFF_H1    (OFF_NBRT + 64 * SROW)         // [128 c][SROW k] (half)
#define OFF_Y2    (OFF_H1 + 128 * SROW)          // [64 ch][SROW k]: 0..31 m, 32..63 h
#define OFF_XH    (OFF_Y2 + 64 * SROW)           // [4 p][256] (also last-reduce scratch)
#define OFF_XN    (OFF_XH + P4 * 256)            // [4 p][64]
#define OFF_MIDX  (OFF_XN + P4 * 64)             // [4 p][32]
#define OFF_XG    (OFF_MIDX + P4 * 32)           // [4 p][64] xn*gate
#define OFF_YBAR  (OFF_XG + P4 * 64)             // [4 p][64]
#define OFF_GATE  (OFF_YBAR + P4 * 64)           // [4 p][128]
#define OFF_LASTX (OFF_GATE + P4 * 128)          // [4 p][32]
#define OFF_NID   (OFF_LASTX + P4 * 32)
#define SMEM_FLOATS (OFF_NID + 64)

__global__ __launch_bounds__(256, 2) void conv_kernel(
    const float* __restrict__ x,
    const float* __restrict__ b1,
    const float* __restrict__ W2, const float* __restrict__ b2,
    const float* __restrict__ Wmid, const float* __restrict__ bmid,
    const float* __restrict__ Wg, const float* __restrict__ bg,
    const float* __restrict__ Wlast, const float* __restrict__ blast,
    float* __restrict__ out)
{
    extern __shared__ float sm[];
    float* sNbrT = sm + OFF_NBRT;
    float* sH1 = sm + OFF_H1;
    float* sY2 = sm + OFF_Y2;
    float* sXh = sm + OFF_XH;
    float* sXn = sm + OFF_XN;
    float* sMidX = sm + OFF_MIDX;
    float* sXg = sm + OFF_XG;
    float* sYbar = sm + OFF_YBAR;
    float* sGate = sm + OFF_GATE;
    float* sLastX = sm + OFF_LASTX;
    int* sNid = (int*)(sm + OFF_NID);

    const int t = threadIdx.x;
    const int g0 = blockIdx.x * P4;
    const int b = g0 >> 12;

    sXn[t] = x[(g0 + (t >> 6)) * 64 + (t & 63)];
    if (t < 64) sNid[t] = g_nbr[g0 * 16 + t];
    __syncthreads();

    // ---- gather neighbors (transposed) + xh (t<128) + mid_x (t>=128) ------
#pragma unroll
    for (int it = 0; it < 4; ++it) {
        const int idx = it * 256 + t;       // 0..1023
        const int kk = idx >> 4;            // 0..63
        const int c4 = (idx & 15) << 2;
        const float4 v = *(const float4*)(x + (b * Nn + sNid[kk]) * 64 + c4);
        sNbrT[(c4 + 0) * SROW + kk] = v.x;
        sNbrT[(c4 + 1) * SROW + kk] = v.y;
        sNbrT[(c4 + 2) * SROW + kk] = v.z;
        sNbrT[(c4 + 3) * SROW + kk] = v.w;
    }
    if (t < 128) {
        // sXh[p][c] = b1[c] + xn[p].W1p[:,c], all 4 points share weight loads
        const int c0 = t;
        float a[4][2];
#pragma unroll
        for (int p = 0; p < 4; ++p) { a[p][0] = 0.f; a[p][1] = 0.f; }
#pragma unroll 4
        for (int j = 0; j < 64; ++j) {
            const float w0 = g_W1p[j * 256 + c0];
            const float w1 = g_W1p[j * 256 + c0 + 128];
#pragma unroll
            for (int p = 0; p < 4; ++p) {
                const float xv = sXn[p * 64 + j];
                a[p][0] = __fmaf_rn(xv, w0, a[p][0]);
                a[p][1] = __fmaf_rn(xv, w1, a[p][1]);
            }
        }
        const float bb0 = b1[c0];
        const float bb1 = b1[c0 + 128];
#pragma unroll
        for (int p = 0; p < 4; ++p) {
            sXh[p * 256 + c0] = a[p][0] + bb0;
            sXh[p * 256 + c0 + 128] = a[p][1] + bb1;
        }
    } else {
        // mid_x[p][c] = xn[p] . Wmid[32:96, c]
        const int p = (t >> 5) & 3;
        const int c = t & 31;
        float a = 0.f;
#pragma unroll 4
        for (int j = 0; j < 64; ++j)
            a = __fmaf_rn(sXn[p * 64 + j], Wmid[(32 + j) * 32 + c], a);
        sMidX[p * 32 + c] = a;
    }
    __syncthreads();

    // ---- GEMM1 + GEMM2 in two 128-column halves ---------------------------
    const int cpair = t & 15;           // GEMM2/mid/last: channels 2cp, 2cp+1
    const int kq = t >> 4;              // 0..15 -> 4 k each
    const int kk2 = kq << 2;
    const int pq = kq >> 2;             // point of this k-quad
    ull g2a00 = 0ull, g2a01 = 0ull, g2a10 = 0ull, g2a11 = 0ull;

#pragma unroll
    for (int h = 0; h < 2; ++h) {
        {   // GEMM1 half: thread 4 cols x 8 k
            const int cg = t >> 3;          // 0..31
            const int kg = t & 7;           // 0..7
            const int kk0 = kg << 3;
            const int p = kg >> 1;
            const int ch0 = h * 128 + cg * 4;
            ull acc[4][4];
#pragma unroll
            for (int c = 0; c < 4; ++c)
#pragma unroll
                for (int kp = 0; kp < 4; ++kp) acc[c][kp] = 0ull;

            const float* wb = g_W1n + ch0;
            const float* ab = sNbrT + kk0;
#pragma unroll 4
            for (int j = 0; j < 64; ++j) {
                const float4 w0 = *(const float4*)(wb + j * 256);
                ull wp[4];
                wp[0] = pack2(w0.x, w0.x); wp[1] = pack2(w0.y, w0.y);
                wp[2] = pack2(w0.z, w0.z); wp[3] = pack2(w0.w, w0.w);
                const ulonglong2 a01 = *(const ulonglong2*)(ab + j * SROW);
                const ulonglong2 a23 = *(const ulonglong2*)(ab + j * SROW + 4);
#pragma unroll
                for (int c = 0; c < 4; ++c) {
                    acc[c][0] = fma2(a01.x, wp[c], acc[c][0]);
                    acc[c][1] = fma2(a01.y, wp[c], acc[c][1]);
                    acc[c][2] = fma2(a23.x, wp[c], acc[c][2]);
                    acc[c][3] = fma2(a23.y, wp[c], acc[c][3]);
                }
            }
#pragma unroll
            for (int c = 0; c < 4; ++c) {
                const int ce = ch0 + c;
                const int cl = cg * 4 + c;
                const float xhv = sXh[p * 256 + ce];
                const float2 u0 = unpack2(acc[c][0]);
                const float2 u1 = unpack2(acc[c][1]);
                const float2 u2 = unpack2(acc[c][2]);
                const float2 u3 = unpack2(acc[c][3]);
                float4 r0, r1;
                r0.x = fmaxf(u0.x + xhv, 0.f); r0.y = fmaxf(u0.y + xhv, 0.f);
                r0.z = fmaxf(u1.x + xhv, 0.f); r0.w = fmaxf(u1.y + xhv, 0.f);
                r1.x = fmaxf(u2.x + xhv, 0.f); r1.y = fmaxf(u2.y + xhv, 0.f);
                r1.z = fmaxf(u3.x + xhv, 0.f); r1.w = fmaxf(u3.y + xhv, 0.f);
                *(float4*)(sH1 + cl * SROW + kk0) = r0;
                *(float4*)(sH1 + cl * SROW + kk0 + 4) = r1;
            }
        }
        __syncthreads();

        {   // GEMM2 partial: j = h*128 .. h*128+127
            const float* w2p = W2 + (h << 12) + 2 * cpair;
#pragma unroll 4
            for (int j = 0; j < 128; ++j) {
                const float2 w = *(const float2*)(w2p + (j << 5));
                const ull wx = pack2(w.x, w.x);
                const ull wy = pack2(w.y, w.y);
                const ulonglong2 av = *(const ulonglong2*)(sH1 + j * SROW + kk2);
                g2a00 = fma2(av.x, wx, g2a00);
                g2a01 = fma2(av.y, wx, g2a01);
                g2a10 = fma2(av.x, wy, g2a10);
                g2a11 = fma2(av.y, wy, g2a11);
            }
        }
        __syncthreads();
    }

    // ---- GEMM2 epilogue -> sY2 rows 32..63 (h) -----------------------------
    {
        const float bbx = b2[2 * cpair];
        const float bby = b2[2 * cpair + 1];
        const float2 u00 = unpack2(g2a00), u01 = unpack2(g2a01);
        const float2 u10 = unpack2(g2a10), u11 = unpack2(g2a11);
        float4 r0, r1;
        r0.x = fmaxf(u00.x + bbx, 0.f); r0.y = fmaxf(u00.y + bbx, 0.f);
        r0.z = fmaxf(u01.x + bbx, 0.f); r0.w = fmaxf(u01.y + bbx, 0.f);
        r1.x = fmaxf(u10.x + bby, 0.f); r1.y = fmaxf(u10.y + bby, 0.f);
        r1.z = fmaxf(u11.x + bby, 0.f); r1.w = fmaxf(u11.y + bby, 0.f);
        *(float4*)(sY2 + (32 + 2 * cpair) * SROW + kk2) = r0;
        *(float4*)(sY2 + (33 + 2 * cpair) * SROW + kk2) = r1;
    }
    __syncthreads();

    // ---- mid: m = relu(h @ Wmid[0:32] + mid_x + bmid) -> sY2 rows 0..31 ----
    {
        ull a00 = 0ull, a01 = 0ull, a10 = 0ull, a11 = 0ull;
#pragma unroll 4
        for (int j = 0; j < 32; ++j) {
            const float2 w = *(const float2*)(Wmid + (j << 5) + 2 * cpair);
            const ull wx = pack2(w.x, w.x);
            const ull wy = pack2(w.y, w.y);
            const ulonglong2 av = *(const ulonglong2*)(sY2 + (32 + j) * SROW + kk2);
            a00 = fma2(av.x, wx, a00);
            a01 = fma2(av.y, wx, a01);
            a10 = fma2(av.x, wy, a10);
            a11 = fma2(av.y, wy, a11);
        }
        const float bx0 = sMidX[pq * 32 + 2 * cpair] + bmid[2 * cpair];
        const float bx1 = sMidX[pq * 32 + 2 * cpair + 1] + bmid[2 * cpair + 1];
        const float2 u00 = unpack2(a00), u01 = unpack2(a01);
        const float2 u10 = unpack2(a10), u11 = unpack2(a11);
        float4 r0, r1;
        r0.x = fmaxf(u00.x + bx0, 0.f); r0.y = fmaxf(u00.y + bx0, 0.f);
        r0.z = fmaxf(u01.x + bx0, 0.f); r0.w = fmaxf(u01.y + bx0, 0.f);
        r1.x = fmaxf(u10.x + bx1, 0.f); r1.y = fmaxf(u10.y + bx1, 0.f);
        r1.z = fmaxf(u11.x + bx1, 0.f); r1.w = fmaxf(u11.y + bx1, 0.f);
        *(float4*)(sY2 + (2 * cpair) * SROW + kk2) = r0;
        *(float4*)(sY2 + (2 * cpair + 1) * SROW + kk2) = r1;
    }
    __syncthreads();

    // ---- ybar = mean_k y2 for the 64 k-dependent channels ------------------
    {
        const int jj = t & 63;
        const int pp = t >> 6;
        const float* row = sY2 + jj * SROW + pp * 16;
        const float4 s0 = *(const float4*)(row + 0);
        const float4 s1 = *(const float4*)(row + 4);
        const float4 s2 = *(const float4*)(row + 8);
        const float4 s3 = *(const float4*)(row + 12);
        const float s = (s0.x + s0.y + s0.z + s0.w) + (s1.x + s1.y + s1.z + s1.w)
                      + (s2.x + s2.y + s2.z + s2.w) + (s3.x + s3.y + s3.z + s3.w);
        sYbar[pp * 64 + jj] = s * (1.0f / 16.0f);
    }
    __syncthreads();

    // ---- gate = sigmoid([ybar, xn] @ Wg + bg); t<128, 2 ch x 2 pts ---------
    if (t < 128) {
        const int c2 = (t & 63) * 2;
        const int p0 = (t >> 6) * 2;
        float a00 = 0.f, a01 = 0.f, a10 = 0.f, a11 = 0.f;
#pragma unroll 4
        for (int j = 0; j < 128; ++j) {
            const float2 w = *(const float2*)(Wg + j * 128 + c2);
            const float y0 = (j < 64) ? sYbar[p0 * 64 + j] : sXn[p0 * 64 + j - 64];
            const float y1 = (j < 64) ? sYbar[(p0 + 1) * 64 + j]
                                      : sXn[(p0 + 1) * 64 + j - 64];
            a00 = __fmaf_rn(y0, w.x, a00);
            a01 = __fmaf_rn(y0, w.y, a01);
            a10 = __fmaf_rn(y1, w.x, a10);
            a11 = __fmaf_rn(y1, w.y, a11);
        }
        const float bb0 = bg[c2];
        const float bb1 = bg[c2 + 1];
        sGate[p0 * 128 + c2] = 1.0f / (1.0f + expf(-(a00 + bb0)));
        sGate[p0 * 128 + c2 + 1] = 1.0f / (1.0f + expf(-(a01 + bb1)));
        sGate[(p0 + 1) * 128 + c2] = 1.0f / (1.0f + expf(-(a10 + bb0)));
        sGate[(p0 + 1) * 128 + c2 + 1] = 1.0f / (1.0f + expf(-(a11 + bb1)));
    }
    __syncthreads();

    // ---- xg = xn*gate; out channels 96..159 (k-invariant, exact) -----------
    {
        const int c = t & 63;
        const int p = t >> 6;
        const float xg = sXn[p * 64 + c] * sGate[p * 128 + 64 + c];
        sXg[p * 64 + c] = xg;
        out[(g0 + p) * 160 + 96 + c] = xg;
    }
    __syncthreads();

    // ---- y2 *= gate; out channels 32..95 = max_k; plus last_x (t<128) ------
    {
        const int jj = t & 63;
        const int pp = t >> 6;
        const float gv = sGate[pp * 128 + jj];
        float* row = sY2 + jj * SROW + pp * 16;
        float mx = -3.0e38f;
#pragma unroll
        for (int q = 0; q < 4; ++q) {
            float4 v = *(const float4*)(row + 4 * q);
            v.x *= gv; v.y *= gv; v.z *= gv; v.w *= gv;
            mx = fmaxf(mx, fmaxf(fmaxf(v.x, v.y), fmaxf(v.z, v.w)));
            *(float4*)(row + 4 * q) = v;
        }
        out[(g0 + pp) * 160 + 32 + jj] = mx;
    }
    if (t < 128) {
        // last_x[p][c] = (xn*gate) . Wlast[64:128, c]
        const int p = t >> 5;
        const int c = t & 31;
        float a = 0.f;
#pragma unroll 4
        for (int j = 0; j < 64; ++j)
            a = __fmaf_rn(sXg[p * 64 + j], Wlast[(64 + j) * 32 + c], a);
        sLastX[p * 32 + c] = a;
    }
    __syncthreads();

    // ---- last (k-dep 64 rows): out ch 0..31 = max_k ------------------------
    float* sRed = sXh;      // reuse as reduce scratch
    {
        ull a00 = 0ull, a01 = 0ull, a10 = 0ull, a11 = 0ull;
#pragma unroll 4
        for (int j = 0; j < 64; ++j) {
            const float2 w = *(const float2*)(Wlast + (j << 5) + 2 * cpair);
            const ull wx = pack2(w.x, w.x);
            const ull wy = pack2(w.y, w.y);
            const ulonglong2 av = *(const ulonglong2*)(sY2 + j * SROW + kk2);
            a00 = fma2(av.x, wx, a00);
            a01 = fma2(av.y, wx, a01);
            a10 = fma2(av.x, wy, a10);
            a11 = fma2(av.y, wy, a11);
        }
        const float t0 = sLastX[pq * 32 + 2 * cpair] + blast[2 * cpair];
        const float t1 = sLastX[pq * 32 + 2 * cpair + 1] + blast[2 * cpair + 1];
        const float2 u00 = unpack2(a00), u01 = unpack2(a01);
        const float2 u10 = unpack2(a10), u11 = unpack2(a11);
        const float mx0 = fmaxf(fmaxf(u00.x + t0, u00.y + t0),
                                fmaxf(u01.x + t0, u01.y + t0));
        const float mx1 = fmaxf(fmaxf(u10.x + t1, u10.y + t1),
                                fmaxf(u11.x + t1, u11.y + t1));
        sRed[kq * 32 + 2 * cpair] = mx0;
        sRed[kq * 32 + 2 * cpair + 1] = mx1;
    }
    __syncthreads();
    if (t < 128) {
        const int p = t >> 5;
        const int cc = t & 31;
        float mx = sRed[(p * 4 + 0) * 32 + cc];
        mx = fmaxf(mx, sRed[(p * 4 + 1) * 32 + cc]);
        mx = fmaxf(mx, sRed[(p * 4 + 2) * 32 + cc]);
        mx = fmaxf(mx, sRed[(p * 4 + 3) * 32 + cc]);
        out[(g0 + p) * 160 + cc] = mx;
    }
}

// ---------------------------------------------------------------------------
extern "C" void kernel_launch(void* const* d_in, const int* in_sizes, int n_in,
                              void* d_out, int out_size) {
    const float* x = (const float*)d_in[0];
    const float* pos = (const float*)d_in[1];
    const float* W1 = (const float*)d_in[2];
    const float* b1 = (const float*)d_in[3];
    const float* W2 = (const float*)d_in[4];
    const float* b2 = (const float*)d_in[5];
    const float* Wmid = (const float*)d_in[6];
    const float* bmid = (const float*)d_in[7];
    const float* Wg = (const float*)d_in[8];
    const float* bg = (const float*)d_in[9];
    const float* Wlast = (const float*)d_in[10];
    const float* blast = (const float*)d_in[11];
    float* out = (float*)d_out;

    const int smem_bytes = SMEM_FLOATS * 4;
    cudaFuncSetAttribute(conv_kernel, cudaFuncAttributeMaxDynamicSharedMemorySize,
                         smem_bytes);

    knn_prep_kernel<<<256 + 128, 128>>>(pos, W1);
    conv_kernel<<<(Bb * Nn) / P4, 256, smem_bytes>>>(
        x, b1, W2, b2, Wmid, bmid, Wg, bg, Wlast, blast, out);
}

// round 9
// speedup vs baseline: 1.5030x; 1.5030x over previous
#include <cuda_runtime.h>
#include <cuda_bf16.h>

#define Bb 8
#define Nn 4096

typedef unsigned long long ull;
typedef unsigned int u32;

// scratch
__device__ int g_nbr[Bb * Nn * 16];
__device__ float g_W1p[64 * 256];       // W1[0:64] - W1[128:192] (x part, fp32)
__device__ uint4 g_W1f[4 * 32 * 32];    // W1n frag-packed bf16 hi/lo
__device__ uint4 g_W2f[16 * 4 * 32];    // W2 frag-packed bf16 hi/lo

// ---------------------------------------------------------------------------
__device__ __forceinline__ void split2(float a, float b, u32& hi, u32& lo) {
    // pack (a -> low half, b -> high half) as bf16x2; hi + lo ~= exact
    __nv_bfloat16 ha = __float2bfloat16_rn(a);
    __nv_bfloat16 hb = __float2bfloat16_rn(b);
    hi = ((u32)__bfloat16_as_ushort(hb) << 16) | (u32)__bfloat16_as_ushort(ha);
    const float ra = a - __bfloat162float(ha);
    const float rb = b - __bfloat162float(hb);
    __nv_bfloat16 la = __float2bfloat16_rn(ra);
    __nv_bfloat16 lb = __float2bfloat16_rn(rb);
    lo = ((u32)__bfloat16_as_ushort(lb) << 16) | (u32)__bfloat16_as_ushort(la);
}

__device__ __forceinline__ void mma_bf16(float* d, u32 a0, u32 a1, u32 a2, u32 a3,
                                         u32 b0, u32 b1) {
    asm volatile(
        "mma.sync.aligned.m16n8k16.row.col.f32.bf16.bf16.f32 "
        "{%0,%1,%2,%3}, {%4,%5,%6,%7}, {%8,%9}, {%0,%1,%2,%3};"
        : "+f"(d[0]), "+f"(d[1]), "+f"(d[2]), "+f"(d[3])
        : "r"(a0), "r"(a1), "r"(a2), "r"(a3), "r"(b0), "r"(b1));
}

// ---------------------------------------------------------------------------
// Kernel 1: KNN (blocks 0..255) + weight prep (blocks 256..383).
// ---------------------------------------------------------------------------
__global__ __launch_bounds__(128) void knn_prep_kernel(const float* __restrict__ pos,
                                                       const float* __restrict__ W1,
                                                       const float* __restrict__ W2) {
    const int bx = blockIdx.x;
    if (bx >= 256) {
        const int i = (bx - 256) * 128 + threadIdx.x;   // 0..16383
        {   // W1p (x-part, fp32)
            const int j = i >> 8;
            const int c = i & 255;
            g_W1p[i] = W1[j * 256 + c] - W1[(128 + j) * 256 + c];
        }
        if (i < 4096) {     // W1n frag pack: [kt 0..3][nt 0..31][lane]
            const int lane = i & 31;
            const int nt = (i >> 5) & 31;
            const int kt = i >> 10;
            const int j0 = kt * 16 + (lane & 3) * 2;
            const int n = nt * 8 + (lane >> 2);
            const float w00 = W1[(64 + j0) * 256 + n] + W1[(128 + j0) * 256 + n];
            const float w01 = W1[(64 + j0 + 1) * 256 + n] + W1[(128 + j0 + 1) * 256 + n];
            const float w10 = W1[(64 + j0 + 8) * 256 + n] + W1[(128 + j0 + 8) * 256 + n];
            const float w11 = W1[(64 + j0 + 9) * 256 + n] + W1[(128 + j0 + 9) * 256 + n];
            u32 h0, l0, h1, l1;
            split2(w00, w01, h0, l0);
            split2(w10, w11, h1, l1);
            g_W1f[i] = make_uint4(h0, h1, l0, l1);
        }
        if (i < 2048) {     // W2 frag pack: [kt 0..15][nt 0..3][lane]
            const int lane = i & 31;
            const int nt = (i >> 5) & 3;
            const int kt = i >> 7;
            const int j0 = kt * 16 + (lane & 3) * 2;
            const int n = nt * 8 + (lane >> 2);
            const float w00 = W2[j0 * 32 + n];
            const float w01 = W2[(j0 + 1) * 32 + n];
            const float w10 = W2[(j0 + 8) * 32 + n];
            const float w11 = W2[(j0 + 9) * 32 + n];
            u32 h0, l0, h1, l1;
            split2(w00, w01, h0, l0);
            split2(w10, w11, h1, l1);
            g_W2f[i] = make_uint4(h0, h1, l0, l1);
        }
        return;
    }

    const int b = bx >> 5;
    const int n = ((bx & 31) << 7) + threadIdx.x;

    const float qx = pos[(b * Nn + n) * 3 + 0];
    const float qy = pos[(b * Nn + n) * 3 + 1];
    const float qz = pos[(b * Nn + n) * 3 + 2];
    const float sqn = __fadd_rn(__fadd_rn(__fmul_rn(qx, qx), __fmul_rn(qy, qy)),
                                __fmul_rn(qz, qz));

    float bd[16];
    int bi[16];
#pragma unroll
    for (int j = 0; j < 16; ++j) { bd[j] = 3.0e38f; bi[j] = 0; }
    float worst = 3.0e38f;
    int wslot = 0;

    __shared__ float4 tile[1024];

    for (int t0 = 0; t0 < Nn; t0 += 1024) {
        __syncthreads();
        for (int i = threadIdx.x; i < 1024; i += 128) {
            const float px = pos[(b * Nn + t0 + i) * 3 + 0];
            const float py = pos[(b * Nn + t0 + i) * 3 + 1];
            const float pz = pos[(b * Nn + t0 + i) * 3 + 2];
            const float sq = __fadd_rn(__fadd_rn(__fmul_rn(px, px), __fmul_rn(py, py)),
                                       __fmul_rn(pz, pz));
            tile[i] = make_float4(px, py, pz, sq);
        }
        __syncthreads();
#pragma unroll 4
        for (int i = 0; i < 1024; ++i) {
            const float4 c = tile[i];
            const int m = t0 + i;
            float dot = __fmaf_rn(qx, c.x, 0.f);
            dot = __fmaf_rn(qy, c.y, dot);
            dot = __fmaf_rn(qz, c.z, dot);
            const float dist = __fsub_rn(__fadd_rn(sqn, c.w), __fmul_rn(2.0f, dot));
            if (dist < worst && m != n) {
#pragma unroll
                for (int j = 0; j < 16; ++j)
                    if (j == wslot) { bd[j] = dist; bi[j] = m; }
                worst = bd[0]; wslot = 0;
#pragma unroll
                for (int j = 1; j < 16; ++j)
                    if (bd[j] > worst) { worst = bd[j]; wslot = j; }
            }
        }
    }

#pragma unroll
    for (int j = 0; j < 16; ++j)
        g_nbr[(b * Nn + n) * 16 + j] = bi[j];
}

// ---------------------------------------------------------------------------
// Kernel 2: fused DenseEdgeConv. 4 points = 64 rows, 256 threads (8 warps).
// GEMM1/GEMM2 on tensor cores (bf16 3-term compensated), rest scalar fp32.
// ---------------------------------------------------------------------------
#define P4 4
#define SROW 68

// u32-unit offsets
#define OFF_AHI   0                          // [64 r][36 kpair]
#define OFF_ALO   (OFF_AHI + 64 * 36)
#define OFF_HHI   (OFF_ALO + 64 * 36)        // [64 r][68 kpair] (half of h1)
#define OFF_HLO   (OFF_HHI + 64 * 68)
#define OFF_Y2    (OFF_HLO + 64 * 68)        // [64 ch][68 kk] fp32
#define OFF_XH    (OFF_Y2 + 64 * 68)         // [4 p][256]
#define OFF_XN    (OFF_XH + P4 * 256)
#define OFF_MIDX  (OFF_XN + P4 * 64)
#define OFF_XG    (OFF_MIDX + P4 * 32)
#define OFF_YBAR  (OFF_XG + P4 * 64)
#define OFF_GATE  (OFF_YBAR + P4 * 64)
#define OFF_LASTX (OFF_GATE + P4 * 128)
#define OFF_NID   (OFF_LASTX + P4 * 32)
#define SMEM_U32  (OFF_NID + 64)

__global__ __launch_bounds__(256, 2) void conv_kernel(
    const float* __restrict__ x,
    const float* __restrict__ b1,
    const float* __restrict__ W2, const float* __restrict__ b2,
    const float* __restrict__ Wmid, const float* __restrict__ bmid,
    const float* __restrict__ Wg, const float* __restrict__ bg,
    const float* __restrict__ Wlast, const float* __restrict__ blast,
    float* __restrict__ out)
{
    extern __shared__ float sm[];
    u32* sAhi = (u32*)sm + OFF_AHI;
    u32* sAlo = (u32*)sm + OFF_ALO;
    u32* sHhi = (u32*)sm + OFF_HHI;
    u32* sHlo = (u32*)sm + OFF_HLO;
    float* sY2 = sm + OFF_Y2;
    float* sXh = sm + OFF_XH;
    float* sXn = sm + OFF_XN;
    float* sMidX = sm + OFF_MIDX;
    float* sXg = sm + OFF_XG;
    float* sYbar = sm + OFF_YBAR;
    float* sGate = sm + OFF_GATE;
    float* sLastX = sm + OFF_LASTX;
    int* sNid = (int*)((u32*)sm + OFF_NID);

    const int t = threadIdx.x;
    const int g0 = blockIdx.x * P4;
    const int b = g0 >> 12;

    sXn[t] = x[(g0 + (t >> 6)) * 64 + (t & 63)];
    if (t < 64) sNid[t] = g_nbr[g0 * 16 + t];
    __syncthreads();

    // ---- gather neighbors -> bf16 hi/lo smem + xh + mid_x -----------------
#pragma unroll
    for (int it = 0; it < 4; ++it) {
        const int idx = it * 256 + t;
        const int kk = idx >> 4;            // 0..63
        const int c4 = (idx & 15) << 2;
        const float4 v = *(const float4*)(x + (b * Nn + sNid[kk]) * 64 + c4);
        u32 h0, l0, h1, l1;
        split2(v.x, v.y, h0, l0);
        split2(v.z, v.w, h1, l1);
        const int base = kk * 36 + (c4 >> 1);
        sAhi[base] = h0; sAhi[base + 1] = h1;
        sAlo[base] = l0; sAlo[base + 1] = l1;
    }
    if (t < 128) {
        const int c0 = t;
        float a[4][2];
#pragma unroll
        for (int p = 0; p < 4; ++p) { a[p][0] = 0.f; a[p][1] = 0.f; }
#pragma unroll 4
        for (int j = 0; j < 64; ++j) {
            const float w0 = g_W1p[j * 256 + c0];
            const float w1 = g_W1p[j * 256 + c0 + 128];
#pragma unroll
            for (int p = 0; p < 4; ++p) {
                const float xv = sXn[p * 64 + j];
                a[p][0] = __fmaf_rn(xv, w0, a[p][0]);
                a[p][1] = __fmaf_rn(xv, w1, a[p][1]);
            }
        }
        const float bb0 = b1[c0];
        const float bb1 = b1[c0 + 128];
#pragma unroll
        for (int p = 0; p < 4; ++p) {
            sXh[p * 256 + c0] = a[p][0] + bb0;
            sXh[p * 256 + c0 + 128] = a[p][1] + bb1;
        }
    } else {
        const int p = (t >> 5) & 3;
        const int c = t & 31;
        float a = 0.f;
#pragma unroll 4
        for (int j = 0; j < 64; ++j)
            a = __fmaf_rn(sXn[p * 64 + j], Wmid[(32 + j) * 32 + c], a);
        sMidX[p * 32 + c] = a;
    }
    __syncthreads();

    // ---- tensor-core GEMM1 + GEMM2 over two 128-col halves ----------------
    const int lane = t & 31;
    const int w = t >> 5;
    const int mt = w & 3;               // m-tile = point
    const int nhw = w >> 2;             // 0..1
    const int lg = lane >> 2;           // group id
    const int lt = lane & 3;            // thread in group

    float d2[2][4];
#pragma unroll
    for (int q = 0; q < 2; ++q)
#pragma unroll
        for (int r = 0; r < 4; ++r) d2[q][r] = 0.f;

#pragma unroll
    for (int h = 0; h < 2; ++h) {
        // GEMM1 half: rows 64 x cols 128 (ntg = h*16 + nhw*8 + nt)
        float d1[8][4];
#pragma unroll
        for (int nt = 0; nt < 8; ++nt)
#pragma unroll
            for (int r = 0; r < 4; ++r) d1[nt][r] = 0.f;

#pragma unroll
        for (int kt = 0; kt < 4; ++kt) {
            const int abase = (mt * 16 + lg) * 36 + kt * 8 + lt;
            const u32 ah0 = sAhi[abase];
            const u32 ah1 = sAhi[abase + 8 * 36];
            const u32 ah2 = sAhi[abase + 4];
            const u32 ah3 = sAhi[abase + 8 * 36 + 4];
            const u32 al0 = sAlo[abase];
            const u32 al1 = sAlo[abase + 8 * 36];
            const u32 al2 = sAlo[abase + 4];
            const u32 al3 = sAlo[abase + 8 * 36 + 4];
#pragma unroll
            for (int nt = 0; nt < 8; ++nt) {
                const int ntg = h * 16 + nhw * 8 + nt;
                const uint4 bb = g_W1f[((kt * 32 + ntg) << 5) + lane];
                mma_bf16(d1[nt], ah0, ah1, ah2, ah3, bb.x, bb.y);
                mma_bf16(d1[nt], ah0, ah1, ah2, ah3, bb.z, bb.w);
                mma_bf16(d1[nt], al0, al1, al2, al3, bb.x, bb.y);
            }
        }
        // epilogue: + xh, relu, bf16-split, store to sH (half layout)
#pragma unroll
        for (int nt = 0; nt < 8; ++nt) {
            const int ntg = h * 16 + nhw * 8 + nt;
            const int c0 = ntg * 8 + 2 * lt;
            const float xh0 = sXh[mt * 256 + c0];
            const float xh1 = sXh[mt * 256 + c0 + 1];
            const float v0 = fmaxf(d1[nt][0] + xh0, 0.f);
            const float v1 = fmaxf(d1[nt][1] + xh1, 0.f);
            const float v2 = fmaxf(d1[nt][2] + xh0, 0.f);
            const float v3 = fmaxf(d1[nt][3] + xh1, 0.f);
            u32 h01, l01, h23, l23;
            split2(v0, v1, h01, l01);
            split2(v2, v3, h23, l23);
            const int pair = (nhw * 8 + nt) * 4 + lt;
            const int r0 = mt * 16 + lg;
            sHhi[r0 * 68 + pair] = h01;
            sHhi[(r0 + 8) * 68 + pair] = h23;
            sHlo[r0 * 68 + pair] = l01;
            sHlo[(r0 + 8) * 68 + pair] = l23;
        }
        __syncthreads();

        // GEMM2 partial: K-tiles ktg = h*8 .. h*8+7
#pragma unroll
        for (int ktl = 0; ktl < 8; ++ktl) {
            const int hbase = (mt * 16 + lg) * 68 + ktl * 8 + lt;
            const u32 ah0 = sHhi[hbase];
            const u32 ah1 = sHhi[hbase + 8 * 68];
            const u32 ah2 = sHhi[hbase + 4];
            const u32 ah3 = sHhi[hbase + 8 * 68 + 4];
            const u32 al0 = sHlo[hbase];
            const u32 al1 = sHlo[hbase + 8 * 68];
            const u32 al2 = sHlo[hbase + 4];
            const u32 al3 = sHlo[hbase + 8 * 68 + 4];
            const int ktg = h * 8 + ktl;
#pragma unroll
            for (int q = 0; q < 2; ++q) {
                const int nt2 = nhw * 2 + q;
                const uint4 bb = g_W2f[((ktg * 4 + nt2) << 5) + lane];
                mma_bf16(d2[q], ah0, ah1, ah2, ah3, bb.x, bb.y);
                mma_bf16(d2[q], ah0, ah1, ah2, ah3, bb.z, bb.w);
                mma_bf16(d2[q], al0, al1, al2, al3, bb.x, bb.y);
            }
        }
        __syncthreads();
    }

    // ---- GEMM2 epilogue -> sY2 rows 32..63 (h), fp32 -----------------------
#pragma unroll
    for (int q = 0; q < 2; ++q) {
        const int nt2 = nhw * 2 + q;
        const int c0 = nt2 * 8 + 2 * lt;
        const int kk0 = mt * 16 + lg;
        const float bb0 = b2[c0];
        const float bb1 = b2[c0 + 1];
        sY2[(32 + c0) * SROW + kk0] = fmaxf(d2[q][0] + bb0, 0.f);
        sY2[(33 + c0) * SROW + kk0] = fmaxf(d2[q][1] + bb1, 0.f);
        sY2[(32 + c0) * SROW + kk0 + 8] = fmaxf(d2[q][2] + bb0, 0.f);
        sY2[(33 + c0) * SROW + kk0 + 8] = fmaxf(d2[q][3] + bb1, 0.f);
    }
    __syncthreads();

    // ---- scalar tail (identical structure to R8) ---------------------------
    const int cpair = t & 15;
    const int kq = t >> 4;
    const int kk2 = kq << 2;
    const int pq = kq >> 2;

    {   // mid: m = relu(h @ Wmid[0:32] + mid_x + bmid) -> sY2 rows 0..31
        float a00 = 0.f, a01 = 0.f, a02 = 0.f, a03 = 0.f;
        float a10 = 0.f, a11 = 0.f, a12 = 0.f, a13 = 0.f;
#pragma unroll 4
        for (int j = 0; j < 32; ++j) {
            const float2 wv = *(const float2*)(Wmid + (j << 5) + 2 * cpair);
            const float4 av = *(const float4*)(sY2 + (32 + j) * SROW + kk2);
            a00 = __fmaf_rn(av.x, wv.x, a00); a01 = __fmaf_rn(av.y, wv.x, a01);
            a02 = __fmaf_rn(av.z, wv.x, a02); a03 = __fmaf_rn(av.w, wv.x, a03);
            a10 = __fmaf_rn(av.x, wv.y, a10); a11 = __fmaf_rn(av.y, wv.y, a11);
            a12 = __fmaf_rn(av.z, wv.y, a12); a13 = __fmaf_rn(av.w, wv.y, a13);
        }
        const float bx0 = sMidX[pq * 32 + 2 * cpair] + bmid[2 * cpair];
        const float bx1 = sMidX[pq * 32 + 2 * cpair + 1] + bmid[2 * cpair + 1];
        float4 r0, r1;
        r0.x = fmaxf(a00 + bx0, 0.f); r0.y = fmaxf(a01 + bx0, 0.f);
        r0.z = fmaxf(a02 + bx0, 0.f); r0.w = fmaxf(a03 + bx0, 0.f);
        r1.x = fmaxf(a10 + bx1, 0.f); r1.y = fmaxf(a11 + bx1, 0.f);
        r1.z = fmaxf(a12 + bx1, 0.f); r1.w = fmaxf(a13 + bx1, 0.f);
        *(float4*)(sY2 + (2 * cpair) * SROW + kk2) = r0;
        *(float4*)(sY2 + (2 * cpair + 1) * SROW + kk2) = r1;
    }
    __syncthreads();

    {   // ybar = mean_k (64 k-dependent channels)
        const int jj = t & 63;
        const int pp = t >> 6;
        const float* row = sY2 + jj * SROW + pp * 16;
        const float4 s0 = *(const float4*)(row + 0);
        const float4 s1 = *(const float4*)(row + 4);
        const float4 s2 = *(const float4*)(row + 8);
        const float4 s3 = *(const float4*)(row + 12);
        const float s = (s0.x + s0.y + s0.z + s0.w) + (s1.x + s1.y + s1.z + s1.w)
                      + (s2.x + s2.y + s2.z + s2.w) + (s3.x + s3.y + s3.z + s3.w);
        sYbar[pp * 64 + jj] = s * (1.0f / 16.0f);
    }
    __syncthreads();

    if (t < 128) {  // gate = sigmoid([ybar, xn] @ Wg + bg)
        const int c2 = (t & 63) * 2;
        const int p0 = (t >> 6) * 2;
        float a00 = 0.f, a01 = 0.f, a10 = 0.f, a11 = 0.f;
#pragma unroll 4
        for (int j = 0; j < 128; ++j) {
            const float2 wv = *(const float2*)(Wg + j * 128 + c2);
            const float y0 = (j < 64) ? sYbar[p0 * 64 + j] : sXn[p0 * 64 + j - 64];
            const float y1 = (j < 64) ? sYbar[(p0 + 1) * 64 + j]
                                      : sXn[(p0 + 1) * 64 + j - 64];
            a00 = __fmaf_rn(y0, wv.x, a00);
            a01 = __fmaf_rn(y0, wv.y, a01);
            a10 = __fmaf_rn(y1, wv.x, a10);
            a11 = __fmaf_rn(y1, wv.y, a11);
        }
        const float bb0 = bg[c2];
        const float bb1 = bg[c2 + 1];
        sGate[p0 * 128 + c2] = 1.0f / (1.0f + expf(-(a00 + bb0)));
        sGate[p0 * 128 + c2 + 1] = 1.0f / (1.0f + expf(-(a01 + bb1)));
        sGate[(p0 + 1) * 128 + c2] = 1.0f / (1.0f + expf(-(a10 + bb0)));
        sGate[(p0 + 1) * 128 + c2 + 1] = 1.0f / (1.0f + expf(-(a11 + bb1)));
    }
    __syncthreads();

    {   // xg = xn*gate; out channels 96..159 (k-invariant)
        const int c = t & 63;
        const int p = t >> 6;
        const float xg = sXn[p * 64 + c] * sGate[p * 128 + 64 + c];
        sXg[p * 64 + c] = xg;
        out[(g0 + p) * 160 + 96 + c] = xg;
    }
    __syncthreads();

    {   // y2 *= gate; out channels 32..95 = max_k
        const int jj = t & 63;
        const int pp = t >> 6;
        const float gv = sGate[pp * 128 + jj];
        float* row = sY2 + jj * SROW + pp * 16;
        float mx = -3.0e38f;
#pragma unroll
        for (int q = 0; q < 4; ++q) {
            float4 v = *(const float4*)(row + 4 * q);
            v.x *= gv; v.y *= gv; v.z *= gv; v.w *= gv;
            mx = fmaxf(mx, fmaxf(fmaxf(v.x, v.y), fmaxf(v.z, v.w)));
            *(float4*)(row + 4 * q) = v;
        }
        out[(g0 + pp) * 160 + 32 + jj] = mx;
    }
    if (t < 128) {  // last_x[p][c] = (xn*gate) . Wlast[64:128, c]
        const int p = t >> 5;
        const int c = t & 31;
        float a = 0.f;
#pragma unroll 4
        for (int j = 0; j < 64; ++j)
            a = __fmaf_rn(sXg[p * 64 + j], Wlast[(64 + j) * 32 + c], a);
        sLastX[p * 32 + c] = a;
    }
    __syncthreads();

    float* sRed = sXh;
    {   // last (k-dep 64 rows): out ch 0..31 = max_k
        float a00 = 0.f, a01 = 0.f, a02 = 0.f, a03 = 0.f;
        float a10 = 0.f, a11 = 0.f, a12 = 0.f, a13 = 0.f;
#pragma unroll 4
        for (int j = 0; j < 64; ++j) {
            const float2 wv = *(const float2*)(Wlast + (j << 5) + 2 * cpair);
            const float4 av = *(const float4*)(sY2 + j * SROW + kk2);
            a00 = __fmaf_rn(av.x, wv.x, a00); a01 = __fmaf_rn(av.y, wv.x, a01);
            a02 = __fmaf_rn(av.z, wv.x, a02); a03 = __fmaf_rn(av.w, wv.x, a03);
            a10 = __fmaf_rn(av.x, wv.y, a10); a11 = __fmaf_rn(av.y, wv.y, a11);
            a12 = __fmaf_rn(av.z, wv.y, a12); a13 = __fmaf_rn(av.w, wv.y, a13);
        }
        const float t0 = sLastX[pq * 32 + 2 * cpair] + blast[2 * cpair];
        const float t1 = sLastX[pq * 32 + 2 * cpair + 1] + blast[2 * cpair + 1];
        const float mx0 = fmaxf(fmaxf(a00 + t0, a01 + t0), fmaxf(a02 + t0, a03 + t0));
        const float mx1 = fmaxf(fmaxf(a10 + t1, a11 + t1), fmaxf(a12 + t1, a13 + t1));
        sRed[kq * 32 + 2 * cpair] = mx0;
        sRed[kq * 32 + 2 * cpair + 1] = mx1;
    }
    __syncthreads();
    if (t < 128) {
        const int p = t >> 5;
        const int cc = t & 31;
        float mx = sRed[(p * 4 + 0) * 32 + cc];
        mx = fmaxf(mx, sRed[(p * 4 + 1) * 32 + cc]);
        mx = fmaxf(mx, sRed[(p * 4 + 2) * 32 + cc]);
        mx = fmaxf(mx, sRed[(p * 4 + 3) * 32 + cc]);
        out[(g0 + p) * 160 + cc] = mx;
    }
}

// ---------------------------------------------------------------------------
extern "C" void kernel_launch(void* const* d_in, const int* in_sizes, int n_in,
                              void* d_out, int out_size) {
    const float* x = (const float*)d_in[0];
    const float* pos = (const float*)d_in[1];
    const float* W1 = (const float*)d_in[2];
    const float* b1 = (const float*)d_in[3];
    const float* W2 = (const float*)d_in[4];
    const float* b2 = (const float*)d_in[5];
    const float* Wmid = (const float*)d_in[6];
    const float* bmid = (const float*)d_in[7];
    const float* Wg = (const float*)d_in[8];
    const float* bg = (const float*)d_in[9];
    const float* Wlast = (const float*)d_in[10];
    const float* blast = (const float*)d_in[11];
    float* out = (float*)d_out;

    const int smem_bytes = SMEM_U32 * 4;
    cudaFuncSetAttribute(conv_kernel, cudaFuncAttributeMaxDynamicSharedMemorySize,
                         smem_bytes);

    knn_prep_kernel<<<256 + 128, 128>>>(pos, W1, W2);
    conv_kernel<<<(Bb * Nn) / P4, 256, smem_bytes>>>(
        x, b1, W2, b2, Wmid, bmid, Wg, bg, Wlast, blast, out);
}